// round 1
// baseline (speedup 1.0000x reference)
#include <cuda_runtime.h>
#include <math.h>

// Problem constants
// B=32, T=256 -> M=8192 rows; E=512, H=512, V=50000
// Gate order i,f,g,o in 4H; f is unused since c0=0.
#define MROWS 8192
#define EDIM  512
#define HDIM  512
#define FOURH 2048

// Tiling
#define BM 64
#define BN 64
#define KT 16
#define NTHREADS 256

// Scratch: per-direction hidden outputs, layout [M][1024] with dir offset d*512
__device__ float g_inp1[MROWS * 1024];  // layer-0 h (both dirs) = layer-1 input
__device__ float g_h1[MROWS * 1024];    // layer-1 h (both dirs)

__device__ __forceinline__ float sigmoidf_(float x) {
    return 1.0f / (1.0f + __expf(-x));
}

// Fused (gather +) GEMM (3 gate blocks) + LSTM activation epilogue.
// Computes, for direction d = blockIdx.z:
//   i = A @ W[d][0:H]^T,  g = A @ W[d][2H:3H]^T,  o = A @ W[d][3H:4H]^T
//   c = sigmoid(i+bi)*tanh(g+bg);  h = sigmoid(o+bo)*tanh(c)
// A is either the embedding gather (layer 0) or g_inp1 (layer 1).
template <int K, bool L0>
__global__ __launch_bounds__(NTHREADS) void lstm_gate_gemm(
    const float* __restrict__ Asrc,   // emb (L0) or unused (L1 uses g_inp1)
    const int*   __restrict__ x,      // tokens (L0 only)
    const float* __restrict__ W,      // (2, 4H, K)
    const float* __restrict__ b_ih,   // (2, 4H)
    const float* __restrict__ b_hh,   // (2, 4H)
    float* __restrict__ hlast,        // [32,512] for this layer (d==0, t==255)
    float* __restrict__ clast)        // [32,512]
{
    __shared__ __align__(16) float As[KT][BM];       // transposed: [k][m]
    __shared__ __align__(16) float Bs[3][KT][BN];    // transposed: [gate][k][h]

    const int tid = threadIdx.x;
    const int m0 = blockIdx.x * BM;
    const int h0 = blockIdx.y * BN;
    const int d  = blockIdx.z;

    const float* Wd = W + (size_t)d * FOURH * K;

    // Loader mapping: each thread loads one float4 per tile per matrix.
    const int lrow = tid >> 2;          // 0..63
    const int lq   = (tid & 3) * 4;     // 0,4,8,12

    const float* arow;
    if (L0) {
        const int tok = x[m0 + lrow];
        arow = Asrc + (size_t)tok * EDIM;
    } else {
        arow = g_inp1 + (size_t)(m0 + lrow) * K;
    }
    const float* brow_i = Wd + (size_t)(h0 + lrow) * K;            // i gate rows
    const float* brow_g = Wd + (size_t)(2 * HDIM + h0 + lrow) * K; // g gate rows
    const float* brow_o = Wd + (size_t)(3 * HDIM + h0 + lrow) * K; // o gate rows

    float acc[3][4][4];
#pragma unroll
    for (int g = 0; g < 3; g++)
#pragma unroll
        for (int i = 0; i < 4; i++)
#pragma unroll
            for (int j = 0; j < 4; j++) acc[g][i][j] = 0.0f;

    const int ty = tid >> 4;   // 0..15 -> m sub-rows
    const int tx = tid & 15;   // 0..15 -> h sub-cols

    for (int k0 = 0; k0 < K; k0 += KT) {
        float4 av = *reinterpret_cast<const float4*>(arow + k0 + lq);
        float4 bi = *reinterpret_cast<const float4*>(brow_i + k0 + lq);
        float4 bg = *reinterpret_cast<const float4*>(brow_g + k0 + lq);
        float4 bo = *reinterpret_cast<const float4*>(brow_o + k0 + lq);
        __syncthreads();
        As[lq + 0][lrow] = av.x; As[lq + 1][lrow] = av.y;
        As[lq + 2][lrow] = av.z; As[lq + 3][lrow] = av.w;
        Bs[0][lq + 0][lrow] = bi.x; Bs[0][lq + 1][lrow] = bi.y;
        Bs[0][lq + 2][lrow] = bi.z; Bs[0][lq + 3][lrow] = bi.w;
        Bs[1][lq + 0][lrow] = bg.x; Bs[1][lq + 1][lrow] = bg.y;
        Bs[1][lq + 2][lrow] = bg.z; Bs[1][lq + 3][lrow] = bg.w;
        Bs[2][lq + 0][lrow] = bo.x; Bs[2][lq + 1][lrow] = bo.y;
        Bs[2][lq + 2][lrow] = bo.z; Bs[2][lq + 3][lrow] = bo.w;
        __syncthreads();

#pragma unroll
        for (int kk = 0; kk < KT; kk++) {
            float4 a4 = *reinterpret_cast<const float4*>(&As[kk][ty * 4]);
            float4 v0 = *reinterpret_cast<const float4*>(&Bs[0][kk][tx * 4]);
            float4 v1 = *reinterpret_cast<const float4*>(&Bs[1][kk][tx * 4]);
            float4 v2 = *reinterpret_cast<const float4*>(&Bs[2][kk][tx * 4]);
            float a[4] = {a4.x, a4.y, a4.z, a4.w};
            float bI[4] = {v0.x, v0.y, v0.z, v0.w};
            float bG[4] = {v1.x, v1.y, v1.z, v1.w};
            float bO[4] = {v2.x, v2.y, v2.z, v2.w};
#pragma unroll
            for (int i = 0; i < 4; i++) {
#pragma unroll
                for (int j = 0; j < 4; j++) {
                    acc[0][i][j] = fmaf(a[i], bI[j], acc[0][i][j]);
                    acc[1][i][j] = fmaf(a[i], bG[j], acc[1][i][j]);
                    acc[2][i][j] = fmaf(a[i], bO[j], acc[2][i][j]);
                }
            }
        }
    }

    // Epilogue
    float* hbuf = L0 ? g_inp1 : g_h1;
#pragma unroll
    for (int j = 0; j < 4; j++) {
        const int h = h0 + tx * 4 + j;
        const float bias_i = b_ih[d * FOURH + h] + b_hh[d * FOURH + h];
        const float bias_g = b_ih[d * FOURH + 2 * HDIM + h] + b_hh[d * FOURH + 2 * HDIM + h];
        const float bias_o = b_ih[d * FOURH + 3 * HDIM + h] + b_hh[d * FOURH + 3 * HDIM + h];
#pragma unroll
        for (int i = 0; i < 4; i++) {
            const int m = m0 + ty * 4 + i;
            const float iv = acc[0][i][j] + bias_i;
            const float gv = acc[1][i][j] + bias_g;
            const float ov = acc[2][i][j] + bias_o;
            const float c  = sigmoidf_(iv) * tanhf(gv);
            const float hv = sigmoidf_(ov) * tanhf(c);
            hbuf[(size_t)m * 1024 + d * HDIM + h] = hv;
            if (d == 0 && (m & 255) == 255) {
                const int b = m >> 8;
                hlast[b * HDIM + h] = hv;
                clast[b * HDIM + h] = c;
            }
        }
    }
}

// encoder_out[b,t,l,h] = h_l_fwd + h_l_bwd ; flat index (m*2 + l)*512 + h
__global__ void combine_kernel(float* __restrict__ enc)
{
    int idx = blockIdx.x * blockDim.x + threadIdx.x;  // over M*H/4 float4s
    const int total = MROWS * HDIM / 4;
    if (idx >= total) return;
    const int m = idx / (HDIM / 4);
    const int h4 = idx - m * (HDIM / 4);   // float4 index within 512

    const float4* r0a = reinterpret_cast<const float4*>(g_inp1 + (size_t)m * 1024) + h4;
    const float4* r0b = reinterpret_cast<const float4*>(g_inp1 + (size_t)m * 1024 + 512) + h4;
    const float4* r1a = reinterpret_cast<const float4*>(g_h1 + (size_t)m * 1024) + h4;
    const float4* r1b = reinterpret_cast<const float4*>(g_h1 + (size_t)m * 1024 + 512) + h4;

    float4 a0 = *r0a, b0 = *r0b, a1 = *r1a, b1 = *r1b;
    float4 v0 = make_float4(a0.x + b0.x, a0.y + b0.y, a0.z + b0.z, a0.w + b0.w);
    float4 v1 = make_float4(a1.x + b1.x, a1.y + b1.y, a1.z + b1.z, a1.w + b1.w);

    float4* e0 = reinterpret_cast<float4*>(enc + ((size_t)m * 2 + 0) * HDIM) + h4;
    float4* e1 = reinterpret_cast<float4*>(enc + ((size_t)m * 2 + 1) * HDIM) + h4;
    *e0 = v0;
    *e1 = v1;
}

extern "C" void kernel_launch(void* const* d_in, const int* in_sizes, int n_in,
                              void* d_out, int out_size)
{
    (void)in_sizes; (void)n_in; (void)out_size;
    const int*   x      = (const int*)d_in[0];
    const float* emb    = (const float*)d_in[1];
    const float* W0     = (const float*)d_in[2];
    // d_in[3] = W_hh_l0 (unused: zero initial hidden state)
    const float* bih0   = (const float*)d_in[4];
    const float* bhh0   = (const float*)d_in[5];
    const float* W1     = (const float*)d_in[6];
    // d_in[7] = W_hh_l1 (unused)
    const float* bih1   = (const float*)d_in[8];
    const float* bhh1   = (const float*)d_in[9];

    float* out   = (float*)d_out;
    float* hlast = out;                      // (2,32,512)
    float* clast = out + 2 * 32 * HDIM;      // (2,32,512)
    float* enc   = out + 4 * 32 * HDIM;      // (32,256,2,512)

    dim3 grid(MROWS / BM, HDIM / BN, 2);
    lstm_gate_gemm<512, true><<<grid, NTHREADS>>>(
        emb, x, W0, bih0, bhh0, hlast, clast);
    lstm_gate_gemm<1024, false><<<grid, NTHREADS>>>(
        nullptr, nullptr, W1, bih1, bhh1, hlast + 32 * HDIM, clast + 32 * HDIM);

    const int total4 = MROWS * HDIM / 4;
    combine_kernel<<<(total4 + 255) / 256, 256>>>(enc);
}

// round 3
// speedup vs baseline: 2.9026x; 2.9026x over previous
#include <cuda_runtime.h>
#include <cuda_bf16.h>
#include <cstdint>
#include <math.h>

// Problem: B=32,T=256 -> M=8192 rows; E=512, H=512; gates i,f,g,o (f unused since c0=0)
#define MROWS 8192
#define HDIM  512

// GEMM tiling
#define BM 128
#define BN 96            // 4 h-blocks of 8, each x3 gates (8-row interleave)
#define BK 32            // bf16 K per chunk (64 bytes per row)
#define NT 256           // 8 warps: 2 (M) x 4 (N)
#define NSTAGE 3
#define A_ST_BYTES 8192          // 128 rows * 64B, per hi/lo
#define B_ST_BYTES 6144          // 96 rows * 64B, per hi/lo
#define STAGE_BYTES (2*A_ST_BYTES + 2*B_ST_BYTES)   // 28672
#define SMEM_TOTAL (NSTAGE * STAGE_BYTES)            // 86016

// ---------------- scratch (device globals; no allocs allowed) ----------------
__device__ __nv_bfloat16 g_A0h[MROWS*512],  g_A0l[MROWS*512];
__device__ __nv_bfloat16 g_A1h[MROWS*1024], g_A1l[MROWS*1024];
__device__ __nv_bfloat16 g_W0h[2*1536*512],  g_W0l[2*1536*512];
__device__ __nv_bfloat16 g_W1h[2*1536*1024], g_W1l[2*1536*1024];
__device__ float g_Bp0[2*1536], g_Bp1[2*1536];
__device__ float g_h0[MROWS*1024], g_h1[MROWS*1024];

// ---------------- PTX helpers (baseline ISA only: sm_80-era) ----------------
__device__ __forceinline__ uint32_t smem_u32(const void* p) {
    uint32_t a;
    asm("{ .reg .u64 t; cvta.to.shared.u64 t, %1; cvt.u32.u64 %0, t; }" : "=r"(a) : "l"(p));
    return a;
}
#define CP_ASYNC16(dst, src) \
    asm volatile("cp.async.cg.shared.global [%0], [%1], 16;" :: "r"(dst), "l"(src))
#define CP_COMMIT() asm volatile("cp.async.commit_group;")
#define CP_WAIT1()  asm volatile("cp.async.wait_group 1;")

#define LDSM_X4(r, addr) \
    asm volatile("ldmatrix.sync.aligned.m8n8.x4.shared.b16 {%0,%1,%2,%3}, [%4];" \
        : "=r"((r)[0]), "=r"((r)[1]), "=r"((r)[2]), "=r"((r)[3]) : "r"(addr))
#define LDSM_X2(r, addr) \
    asm volatile("ldmatrix.sync.aligned.m8n8.x2.shared.b16 {%0,%1}, [%2];" \
        : "=r"((r)[0]), "=r"((r)[1]) : "r"(addr))

#define MMA16816(d, a, b) \
    asm volatile("mma.sync.aligned.m16n8k16.row.col.f32.bf16.bf16.f32 " \
        "{%0,%1,%2,%3}, {%4,%5,%6,%7}, {%8,%9}, {%0,%1,%2,%3};" \
        : "+f"((d)[0]), "+f"((d)[1]), "+f"((d)[2]), "+f"((d)[3]) \
        : "r"((a)[0]), "r"((a)[1]), "r"((a)[2]), "r"((a)[3]), "r"((b)[0]), "r"((b)[1]))

__device__ __forceinline__ float sig_(float x) { return 1.0f / (1.0f + __expf(-x)); }

// 64B rows, 4x16B chunks; conflict-free swizzle for both cp.async and ldmatrix
__device__ __forceinline__ uint32_t swz64(int row, int chunk) {
    return (uint32_t)(row * 64 + ((chunk ^ ((row >> 1) & 3)) << 4));
}

// ---------------- prep kernels ----------------
// Gather emb rows by token, split fp32 -> bf16 hi + lo.
__global__ void gather_split(const int* __restrict__ x, const float* __restrict__ emb)
{
    int id = blockIdx.x * blockDim.x + threadIdx.x;   // over MROWS*128 float4s
    if (id >= MROWS * 128) return;
    int m  = id >> 7;
    int c4 = id & 127;
    int tok = x[m];
    float4 v = *(reinterpret_cast<const float4*>(emb + (size_t)tok * 512) + c4);
    float vv[4] = {v.x, v.y, v.z, v.w};
    size_t o = (size_t)m * 512 + c4 * 4;
#pragma unroll
    for (int q = 0; q < 4; q++) {
        __nv_bfloat16 hi = __float2bfloat16_rn(vv[q]);
        g_A0h[o + q] = hi;
        g_A0l[o + q] = __float2bfloat16_rn(vv[q] - __bfloat162float(hi));
    }
}

// Pack weights, gate-interleaved at n8 granularity:
//   packed row p = hb*24 + gate*8 + hi, h = hb*8 + hi, gates {i,g,o} <- src rows {0,2,3}
// Split fp32 -> bf16 hi/lo; also pack combined biases with the same p index.
template <int K, int LAYER>
__global__ void pack_w(const float* __restrict__ W,
                       const float* __restrict__ bih, const float* __restrict__ bhh)
{
    __nv_bfloat16* Wh = LAYER ? g_W1h : g_W0h;
    __nv_bfloat16* Wl = LAYER ? g_W1l : g_W0l;
    float*         Bp = LAYER ? g_Bp1 : g_Bp0;

    const int KQ = K / 4;
    int id = blockIdx.x * blockDim.x + threadIdx.x;   // over 2*1536*KQ
    if (id >= 2 * 1536 * KQ) return;
    int dir = id / (1536 * KQ);
    int rem = id - dir * 1536 * KQ;
    int p   = rem / KQ;
    int c4  = rem - p * KQ;
    int hb   = p / 24;
    int w    = p - hb * 24;
    int gate = w >> 3;
    int hi   = w & 7;
    int h    = hb * 8 + hi;
    int gsrc = (gate == 0) ? 0 : (gate + 1);   // i->0, g->2, o->3
    size_t src = ((size_t)dir * 2048 + gsrc * 512 + h) * K + c4 * 4;
    size_t dst = ((size_t)dir * 1536 + p) * K + c4 * 4;
    float4 v = *reinterpret_cast<const float4*>(W + src);
    float vv[4] = {v.x, v.y, v.z, v.w};
#pragma unroll
    for (int q = 0; q < 4; q++) {
        __nv_bfloat16 h16 = __float2bfloat16_rn(vv[q]);
        Wh[dst + q] = h16;
        Wl[dst + q] = __float2bfloat16_rn(vv[q] - __bfloat162float(h16));
    }
    if (c4 == 0) {
        int bi = dir * 2048 + gsrc * 512 + h;
        Bp[dir * 1536 + p] = bih[bi] + bhh[bi];
    }
}

// ---------------- fused split-bf16 GEMM (mma.sync) + LSTM epilogue ----------------
template <int K, int LAYER>
__global__ __launch_bounds__(NT) void gemm_lstm(float* __restrict__ hlast,
                                                float* __restrict__ clast)
{
    extern __shared__ char smem[];
    const uint32_t sb = smem_u32(smem);

    const int tid = threadIdx.x;
    const int wid = tid >> 5;
    const int lid = tid & 31;
    const int warpM = wid >> 2;          // 0..1
    const int warpN = wid & 3;           // 0..3

    const int m0 = blockIdx.x * BM;
    const int by = blockIdx.y;           // 16 n-tiles of 96 packed rows
    const int d  = blockIdx.z;

    const __nv_bfloat16* Ah = LAYER ? g_A1h : g_A0h;
    const __nv_bfloat16* Al = LAYER ? g_A1l : g_A0l;
    const __nv_bfloat16* Wh = LAYER ? g_W1h : g_W0h;
    const __nv_bfloat16* Wl = LAYER ? g_W1l : g_W0l;
    const float*         Bp = LAYER ? g_Bp1 : g_Bp0;
    const int nrow0 = d * 1536 + by * BN;

    constexpr int NCH = K / BK;

    float acc[4][3][4];
#pragma unroll
    for (int mf = 0; mf < 4; mf++)
#pragma unroll
        for (int g = 0; g < 3; g++)
#pragma unroll
            for (int q = 0; q < 4; q++) acc[mf][g][q] = 0.0f;

    // Loader: A = 1024 x 16B (hi,lo), B = 768 x 16B (hi,lo) per stage
    auto issue = [&](int kc, int stage) {
        if (kc >= NCH) return;
        const uint32_t so = sb + stage * STAGE_BYTES;
        const int k0 = kc * BK;
#pragma unroll
        for (int it = 0; it < 4; it++) {
            int idx = tid + it * NT;
            int arr = idx >> 9;
            int rem = idx & 511;
            int row = rem >> 2;
            int c   = rem & 3;
            const __nv_bfloat16* g = (arr ? Al : Ah) + (size_t)(m0 + row) * K + k0 + c * 8;
            CP_ASYNC16(so + arr * A_ST_BYTES + swz64(row, c), g);
        }
#pragma unroll
        for (int it = 0; it < 3; it++) {
            int idx = tid + it * NT;
            int arr = (idx >= 384) ? 1 : 0;
            int rem = idx - arr * 384;
            int row = rem >> 2;
            int c   = rem & 3;
            const __nv_bfloat16* g = (arr ? Wl : Wh) + (size_t)(nrow0 + row) * K + k0 + c * 8;
            CP_ASYNC16(so + 2 * A_ST_BYTES + arr * B_ST_BYTES + swz64(row, c), g);
        }
    };

    issue(0, 0); CP_COMMIT();
    issue(1, 1); CP_COMMIT();

    // per-lane ldmatrix address components
    const int la_row = (lid & 7) + ((lid >> 3) & 1) * 8;   // A: m within frag
    const int la_ch  = (lid >> 4);                          // A: k-half select
    const int lb_row = (lid & 7) + ((lid >> 4) << 3);       // B x4: n within pair
    const int lb_ch  = ((lid >> 3) & 1);                    // B: k-half select
    const int lo_row = 16 + (lid & 7);                      // B x2 (gate o)

    for (int kc = 0; kc < NCH; kc++) {
        CP_WAIT1();
        __syncthreads();
        issue(kc + 2, (kc + 2) % NSTAGE); CP_COMMIT();

        const uint32_t sA = sb + (kc % NSTAGE) * STAGE_BYTES;
        const uint32_t sB = sA + 2 * A_ST_BYTES;

#pragma unroll
        for (int kg = 0; kg < 2; kg++) {
            uint32_t aH[4][4], aL[4][4], bH[3][2], bL[3][2];
#pragma unroll
            for (int mf = 0; mf < 4; mf++) {
                int row = warpM * 64 + mf * 16 + la_row;
                uint32_t addr = sA + swz64(row, kg * 2 + la_ch);
                LDSM_X4(aH[mf], addr);
                LDSM_X4(aL[mf], addr + A_ST_BYTES);
            }
            {
                int row = warpN * 24 + lb_row;
                uint32_t addr = sB + swz64(row, kg * 2 + lb_ch);
                uint32_t t[4];
                LDSM_X4(t, addr);
                bH[0][0] = t[0]; bH[0][1] = t[1]; bH[1][0] = t[2]; bH[1][1] = t[3];
                LDSM_X4(t, addr + B_ST_BYTES);
                bL[0][0] = t[0]; bL[0][1] = t[1]; bL[1][0] = t[2]; bL[1][1] = t[3];
                int rowo = warpN * 24 + lo_row;
                uint32_t addro = sB + swz64(rowo, kg * 2 + lb_ch);
                LDSM_X2(bH[2], addro);
                LDSM_X2(bL[2], addro + B_ST_BYTES);
            }
#pragma unroll
            for (int mf = 0; mf < 4; mf++)
#pragma unroll
                for (int g = 0; g < 3; g++) MMA16816(acc[mf][g], aH[mf], bH[g]);
#pragma unroll
            for (int mf = 0; mf < 4; mf++)
#pragma unroll
                for (int g = 0; g < 3; g++) MMA16816(acc[mf][g], aH[mf], bL[g]);
#pragma unroll
            for (int mf = 0; mf < 4; mf++)
#pragma unroll
                for (int g = 0; g < 3; g++) MMA16816(acc[mf][g], aL[mf], bH[g]);
        }
    }

    // -------- fused LSTM epilogue (thread-local across gates) --------
    const int r  = lid >> 2;
    const int c0 = (lid & 3) * 2;
    const int hb = by * 4 + warpN;          // h-block of 8
    const int pb = d * 1536 + hb * 24;
    float* ghbuf = LAYER ? g_h1 : g_h0;

#pragma unroll
    for (int mf = 0; mf < 4; mf++) {
#pragma unroll
        for (int rr = 0; rr < 2; rr++) {
            const int m = m0 + warpM * 64 + mf * 16 + rr * 8 + r;
#pragma unroll
            for (int cc = 0; cc < 2; cc++) {
                const int hi = c0 + cc;
                const int h  = hb * 8 + hi;
                const int q  = rr * 2 + cc;
                float iv = acc[mf][0][q] + __ldg(&Bp[pb + hi]);
                float gv = acc[mf][1][q] + __ldg(&Bp[pb + 8 + hi]);
                float ov = acc[mf][2][q] + __ldg(&Bp[pb + 16 + hi]);
                float cv = sig_(iv) * tanhf(gv);
                float hv = sig_(ov) * tanhf(cv);
                size_t o = (size_t)m * 1024 + d * HDIM + h;
                ghbuf[o] = hv;
                if (LAYER == 0) {
                    __nv_bfloat16 hh = __float2bfloat16_rn(hv);
                    g_A1h[o] = hh;
                    g_A1l[o] = __float2bfloat16_rn(hv - __bfloat162float(hh));
                }
                if (d == 0 && (m & 255) == 255) {
                    hlast[(m >> 8) * HDIM + h] = hv;
                    clast[(m >> 8) * HDIM + h] = cv;
                }
            }
        }
    }
}

// ---------------- combine: enc[b,t,l,h] = h_fwd + h_bwd ----------------
__global__ void combine_kernel(float* __restrict__ enc)
{
    int idx = blockIdx.x * blockDim.x + threadIdx.x;
    const int total = MROWS * HDIM / 4;
    if (idx >= total) return;
    const int m  = idx / (HDIM / 4);
    const int h4 = idx - m * (HDIM / 4);

    const float4* r0a = reinterpret_cast<const float4*>(g_h0 + (size_t)m * 1024) + h4;
    const float4* r0b = reinterpret_cast<const float4*>(g_h0 + (size_t)m * 1024 + 512) + h4;
    const float4* r1a = reinterpret_cast<const float4*>(g_h1 + (size_t)m * 1024) + h4;
    const float4* r1b = reinterpret_cast<const float4*>(g_h1 + (size_t)m * 1024 + 512) + h4;
    float4 a0 = *r0a, b0 = *r0b, a1 = *r1a, b1 = *r1b;
    float4 v0 = make_float4(a0.x + b0.x, a0.y + b0.y, a0.z + b0.z, a0.w + b0.w);
    float4 v1 = make_float4(a1.x + b1.x, a1.y + b1.y, a1.z + b1.z, a1.w + b1.w);
    *(reinterpret_cast<float4*>(enc + ((size_t)m * 2 + 0) * HDIM) + h4) = v0;
    *(reinterpret_cast<float4*>(enc + ((size_t)m * 2 + 1) * HDIM) + h4) = v1;
}

extern "C" void kernel_launch(void* const* d_in, const int* in_sizes, int n_in,
                              void* d_out, int out_size)
{
    (void)in_sizes; (void)n_in; (void)out_size;
    const int*   x    = (const int*)d_in[0];
    const float* emb  = (const float*)d_in[1];
    const float* W0   = (const float*)d_in[2];
    const float* bih0 = (const float*)d_in[4];
    const float* bhh0 = (const float*)d_in[5];
    const float* W1   = (const float*)d_in[6];
    const float* bih1 = (const float*)d_in[8];
    const float* bhh1 = (const float*)d_in[9];

    float* out   = (float*)d_out;
    float* hlast = out;                      // (2,32,512)
    float* clast = out + 2 * 32 * HDIM;      // (2,32,512)
    float* enc   = out + 4 * 32 * HDIM;      // (32,256,2,512)

    cudaFuncSetAttribute(gemm_lstm<512, 0>,  cudaFuncAttributeMaxDynamicSharedMemorySize, SMEM_TOTAL);
    cudaFuncSetAttribute(gemm_lstm<1024, 1>, cudaFuncAttributeMaxDynamicSharedMemorySize, SMEM_TOTAL);

    gather_split<<<(MROWS * 128 + 255) / 256, 256>>>(x, emb);
    pack_w<512, 0><<<(2 * 1536 * 128 + 255) / 256, 256>>>(W0, bih0, bhh0);
    pack_w<1024, 1><<<(2 * 1536 * 256 + 255) / 256, 256>>>(W1, bih1, bhh1);

    dim3 grid(MROWS / BM, 1536 / BN, 2);
    gemm_lstm<512, 0><<<grid, NT, SMEM_TOTAL>>>(hlast, clast);
    gemm_lstm<1024, 1><<<grid, NT, SMEM_TOTAL>>>(hlast + 32 * HDIM, clast + 32 * HDIM);

    combine_kernel<<<(MROWS * HDIM / 4 + 255) / 256, 256>>>(enc);
}